// round 3
// baseline (speedup 1.0000x reference)
#include <cuda_runtime.h>
#include <math.h>

#define B_ 4
#define N_ 8192

constexpr int TPB    = 256;            // threads per block (chamfer)
constexpr int PPT    = 8;              // x points per thread
constexpr int XPB    = TPB * PPT;      // 2048 x per block
constexpr int XT     = N_ / XPB;       // 4 x tiles
constexpr int SEG    = 256;            // y per block
constexpr int SEGS   = N_ / SEG;       // 32 y segments
constexpr int NWARP  = TPB / 32;       // 8
constexpr int SL_GRID = 256;           // small-loss blocks
constexpr int FTPB   = 1024;           // finalize threads

// Scratch: min-d2 int-encoded (nonneg floats -> int compare valid), partials.
// [0, B*N)        : pred-side mins (min over targ)
// [B*N, 2*B*N)    : targ-side mins (min over pred)
__device__ int   g_min[2 * B_ * N_];
__device__ float g_part[3 * SL_GRID];

union F2 { unsigned long long u; float2 f; };

__device__ __forceinline__ unsigned long long fma2(unsigned long long a,
                                                   unsigned long long b,
                                                   unsigned long long c) {
    unsigned long long d;
    asm("fma.rn.f32x2 %0, %1, %2, %3;" : "=l"(d) : "l"(a), "l"(b), "l"(c));
    return d;
}
__device__ __forceinline__ unsigned long long add2(unsigned long long a,
                                                   unsigned long long b) {
    unsigned long long d;
    asm("add.rn.f32x2 %0, %1, %2;" : "=l"(d) : "l"(a), "l"(b));
    return d;
}

// ---------------- small losses + g_min init (one launch) ----------------
__global__ void small_losses_kernel(const float* __restrict__ pred,
                                    const float* __restrict__ targ) {
    __shared__ float red[TPB];
    const int tid = threadIdx.x;
    const int gid = blockIdx.x * TPB + tid;
    const int gsz = gridDim.x * TPB;     // 65536

    // init chamfer min slots (2*B*N = 65536 ints, one per thread)
    g_min[gid] = 0x7F7F7F7F;

    // ---- vertex: sum (p-t)^2, float4 (24576 float4) ----
    const float4* p4 = (const float4*)pred;
    const float4* t4 = (const float4*)targ;
    float s = 0.f;
    for (int i = gid; i < B_ * N_ * 3 / 4; i += gsz) {
        float4 a = p4[i], b = t4[i];
        float d0 = a.x - b.x, d1 = a.y - b.y, d2 = a.z - b.z, d3 = a.w - b.w;
        s = fmaf(d0, d0, fmaf(d1, d1, fmaf(d2, d2, fmaf(d3, d3, s))));
    }
    red[tid] = s; __syncthreads();
    for (int o = TPB / 2; o > 0; o >>= 1) {
        if (tid < o) red[tid] += red[tid + o];
        __syncthreads();
    }
    if (tid == 0) g_part[0 * SL_GRID + blockIdx.x] = red[0];
    __syncthreads();

    // ---- smoothness ----
    s = 0.f;
    for (int b = 0; b < B_; b++) {
        const float* pb = pred + b * N_ * 3;
        for (int k = gid; k < N_ - 1; k += gsz) {
            const float* p = pb + k * 3;
            float dx = p[3] - p[0], dy = p[4] - p[1], dz = p[5] - p[2];
            s += sqrtf(fmaf(dx, dx, fmaf(dy, dy, dz * dz)));
        }
    }
    red[tid] = s; __syncthreads();
    for (int o = TPB / 2; o > 0; o >>= 1) {
        if (tid < o) red[tid] += red[tid + o];
        __syncthreads();
    }
    if (tid == 0) g_part[1 * SL_GRID + blockIdx.x] = red[0];
    __syncthreads();

    // ---- symmetry ----
    s = 0.f;
    const int mid = N_ / 2;
    for (int b = 0; b < B_; b++) {
        const float* pb = pred + b * N_ * 3;
        for (int k = gid; k < mid; k += gsz) {
            const float* l = pb + k * 3;
            const float* r = pb + (N_ - 1 - k) * 3;
            float d0 = l[0] + r[0];
            float d1 = l[1] - r[1];
            float d2 = l[2] - r[2];
            s += fmaf(d0, d0, fmaf(d1, d1, d2 * d2));
        }
    }
    red[tid] = s; __syncthreads();
    for (int o = TPB / 2; o > 0; o >>= 1) {
        if (tid < o) red[tid] += red[tid + o];
        __syncthreads();
    }
    if (tid == 0) g_part[2 * SL_GRID + blockIdx.x] = red[0];
}

// ---------------- symmetric-fused chamfer: both directions, one pass ----------------
// Block tile: 2048 pred points (regs, 8/thread) x 256 targ points (smem).
// d2 = (xn + yw) - 2 x.y  via ADD2 base + 3-deep packed-FMA chain (2 x per inst).
// Row mins (pred side) in registers. Col mins (targ side): lane rotation
// j = (t + lane) & 255 -> warp-private smem array, race-free, merged at end.
__global__ void __launch_bounds__(TPB, 4)
chamfer_kernel(const float* __restrict__ pred, const float* __restrict__ targ) {
    __shared__ F2 syA[SEG][2];          // {-2y0 dup, -2y1 dup}   4KB
    __shared__ F2 syB[SEG][2];          // {-2y2 dup,  yw  dup}   4KB
    __shared__ float scol[NWARP][SEG];  // warp-private col mins  8KB

    const int tid  = threadIdx.x;
    const int lane = tid & 31;
    const int wid  = tid >> 5;
    const int b    = blockIdx.z;

    // load + fold targ segment
    const float* Yb = targ + b * N_ * 3;
    const int m0 = blockIdx.y * SEG;
    for (int j = tid; j < SEG; j += TPB) {
        const float* y = Yb + (m0 + j) * 3;
        float y0 = y[0], y1 = y[1], y2 = y[2];
        float yw = fmaf(y0, y0, fmaf(y1, y1, y2 * y2));
        F2 a, bb, c, d;
        a.f  = make_float2(-2.f * y0, -2.f * y0);
        bb.f = make_float2(-2.f * y1, -2.f * y1);
        c.f  = make_float2(-2.f * y2, -2.f * y2);
        d.f  = make_float2(yw, yw);
        syA[j][0] = a; syA[j][1] = bb;
        syB[j][0] = c; syB[j][1] = d;
    }
    for (int j = tid; j < NWARP * SEG; j += TPB)
        ((float*)scol)[j] = 3.0e38f;
    __syncthreads();

    // load 8 pred points per thread, packed as 4 pairs (q, q+4)
    const float* Xb = pred + b * N_ * 3;
    const int base = blockIdx.x * XPB + tid;

    F2 xp0[4], xp1[4], xp2[4], xnp[4];
    float rmA[4], rmB[4];
#pragma unroll
    for (int q = 0; q < 4; q++) {
        const float* xa = Xb + (base + q * TPB) * 3;
        const float* xb = Xb + (base + (q + 4) * TPB) * 3;
        float a0 = xa[0], a1 = xa[1], a2 = xa[2];
        float b0 = xb[0], b1 = xb[1], b2 = xb[2];
        xp0[q].f = make_float2(a0, b0);
        xp1[q].f = make_float2(a1, b1);
        xp2[q].f = make_float2(a2, b2);
        xnp[q].f = make_float2(fmaf(a0, a0, fmaf(a1, a1, a2 * a2)),
                               fmaf(b0, b0, fmaf(b1, b1, b2 * b2)));
        rmA[q] = 3.0e38f; rmB[q] = 3.0e38f;
    }

    // mainloop: each lane rotates through all 256 y's; distinct j per lane
    // at every step -> scol[wid][j] is race-free.
#pragma unroll 4
    for (int t = 0; t < SEG; t++) {
        const int j = (t + lane) & (SEG - 1);
        ulonglong2 r0 = *(const ulonglong2*)&syA[j][0];  // {-2y0 | -2y1}
        ulonglong2 r1 = *(const ulonglong2*)&syB[j][0];  // {-2y2 |  yw }
        float cm = scol[wid][j];
        float acc = 3.0e38f;
#pragma unroll
        for (int q = 0; q < 4; q++) {
            F2 d;
            d.u = fma2(xp0[q].u, r0.x,
                   fma2(xp1[q].u, r0.y,
                    fma2(xp2[q].u, r1.x, add2(xnp[q].u, r1.y))));
            rmA[q] = fminf(rmA[q], d.f.x);
            rmB[q] = fminf(rmB[q], d.f.y);
            acc = fminf(acc, fminf(d.f.x, d.f.y));
        }
        scol[wid][j] = fminf(cm, acc);
    }

    // row (pred-side) results
#pragma unroll
    for (int q = 0; q < 4; q++) {
        atomicMin(&g_min[b * N_ + base + q * TPB],
                  __float_as_int(fmaxf(rmA[q], 0.f)));
        atomicMin(&g_min[b * N_ + base + (q + 4) * TPB],
                  __float_as_int(fmaxf(rmB[q], 0.f)));
    }

    // col (targ-side): merge 8 warp-private arrays (SEG == TPB)
    __syncthreads();
    {
        float m = scol[0][tid];
#pragma unroll
        for (int w = 1; w < NWARP; w++) m = fminf(m, scol[w][tid]);
        atomicMin(&g_min[B_ * N_ + b * N_ + m0 + tid],
                  __float_as_int(fmaxf(m, 0.f)));
    }
}

// ---------------- finalize ----------------
__global__ void finalize_kernel(float* __restrict__ out) {
    __shared__ float red[FTPB];
    __shared__ float sums[4];
    const int tid = threadIdx.x;

    float s = 0.f;
    const int4* gm4 = (const int4*)g_min;
    for (int i = tid; i < 2 * B_ * N_ / 4; i += FTPB) {
        int4 v = gm4[i];
        s += sqrtf(__int_as_float(v.x)) + sqrtf(__int_as_float(v.y))
           + sqrtf(__int_as_float(v.z)) + sqrtf(__int_as_float(v.w));
    }
    red[tid] = s; __syncthreads();
    for (int o = FTPB / 2; o > 0; o >>= 1) {
        if (tid < o) red[tid] += red[tid + o];
        __syncthreads();
    }
    if (tid == 0) sums[3] = red[0];
    __syncthreads();

#pragma unroll
    for (int t = 0; t < 3; t++) {
        s = (tid < SL_GRID) ? g_part[t * SL_GRID + tid] : 0.f;
        red[tid] = s; __syncthreads();
        for (int o = FTPB / 2; o > 0; o >>= 1) {
            if (tid < o) red[tid] += red[tid + o];
            __syncthreads();
        }
        if (tid == 0) sums[t] = red[0];
        __syncthreads();
    }

    if (tid == 0) {
        float vertex_loss  = sums[0] / (float)(B_ * N_ * 3);
        float smooth_loss  = sums[1] / (float)(B_ * (N_ - 1));
        float sym_loss     = sums[2] / (float)(B_ * (N_ / 2) * 3);
        float chamfer_loss = sums[3] / (float)(B_ * N_);
        out[0] = 1.0f * vertex_loss + 0.1f * smooth_loss
               + 0.05f * sym_loss + 0.1f * chamfer_loss;
    }
}

extern "C" void kernel_launch(void* const* d_in, const int* in_sizes, int n_in,
                              void* d_out, int out_size) {
    const float* pred = (const float*)d_in[0];
    const float* targ = (const float*)d_in[1];
    float* out = (float*)d_out;
    (void)in_sizes; (void)n_in; (void)out_size;

    small_losses_kernel<<<SL_GRID, TPB>>>(pred, targ);   // also inits g_min

    dim3 grid(XT, SEGS, B_);                             // 4 x 32 x 4 = 512
    chamfer_kernel<<<grid, TPB>>>(pred, targ);

    finalize_kernel<<<1, FTPB>>>(out);
}

// round 5
// speedup vs baseline: 1.6288x; 1.6288x over previous
#include <cuda_runtime.h>
#include <math.h>

#define B_ 4
#define N_ 8192

constexpr int TPB   = 256;
constexpr int SEG   = 512;              // y points per block
constexpr int YS    = N_ / SEG;         // 16 y segments
constexpr int XPB   = 1024;             // x points per block
constexpr int XT    = N_ / XPB;         // 8 x tiles
constexpr int NWARP = TPB / 32;         // 8
constexpr int CHAM_BLOCKS = XT * YS * B_;   // 512
constexpr int SL_BLOCKS   = 64;
constexpr int RED_BLOCKS  = 64;

// Partial-min scratch: every slot written exactly once per call (no init, no atomics).
__device__ float g_rowpart[YS * B_ * N_];   // pred-side mins, per y-segment
__device__ float g_colpart[XT * B_ * N_];   // targ-side mins, per x-tile
__device__ float g_part[3 * SL_BLOCKS];     // small-loss block partials
__device__ float g_part2[RED_BLOCKS];       // chamfer sqrt-sum block partials

union F2 { unsigned long long u; float2 f; };

__device__ __forceinline__ unsigned long long fma2(unsigned long long a,
                                                   unsigned long long b,
                                                   unsigned long long c) {
    unsigned long long d;
    asm("fma.rn.f32x2 %0, %1, %2, %3;" : "=l"(d) : "l"(a), "l"(b), "l"(c));
    return d;
}
__device__ __forceinline__ unsigned long long add2(unsigned long long a,
                                                   unsigned long long b) {
    unsigned long long d;
    asm("add.rn.f32x2 %0, %1, %2;" : "=l"(d) : "l"(a), "l"(b));
    return d;
}
__device__ __forceinline__ unsigned long long dup2(float v) {
    F2 r; r.f = make_float2(v, v); return r.u;
}

// ---------------- megakernel: 64 small-loss blocks + 512 chamfer blocks ----------------
__global__ void __launch_bounds__(TPB, 4)
mega_kernel(const float* __restrict__ pred, const float* __restrict__ targ) {
    // 32 bytes per y row: [0]=-2y0 dup, [1]=-2y1 dup, [2]=-2y2 dup, [3]=yw dup
    __shared__ __align__(16) unsigned long long sy[SEG][4];   // 16KB
    __shared__ float scol[NWARP][SEG];                        // 16KB
    __shared__ float red[TPB];                                //  1KB

    const int tid = threadIdx.x;

    if (blockIdx.x < SL_BLOCKS) {
        // ======== small losses (hidden under chamfer blocks) ========
        const int gid = blockIdx.x * TPB + tid;
        const int gsz = SL_BLOCKS * TPB;          // 16384

        // vertex MSE, float4
        const float4* p4 = (const float4*)pred;
        const float4* t4 = (const float4*)targ;
        float s = 0.f;
        for (int i = gid; i < B_ * N_ * 3 / 4; i += gsz) {
            float4 a = p4[i], b = t4[i];
            float d0 = a.x - b.x, d1 = a.y - b.y, d2 = a.z - b.z, d3 = a.w - b.w;
            s = fmaf(d0, d0, fmaf(d1, d1, fmaf(d2, d2, fmaf(d3, d3, s))));
        }
        red[tid] = s; __syncthreads();
        for (int o = TPB / 2; o > 0; o >>= 1) {
            if (tid < o) red[tid] += red[tid + o];
            __syncthreads();
        }
        if (tid == 0) g_part[0 * SL_BLOCKS + blockIdx.x] = red[0];
        __syncthreads();

        // smoothness
        s = 0.f;
        for (int b = 0; b < B_; b++) {
            const float* pb = pred + b * N_ * 3;
            for (int k = gid; k < N_ - 1; k += gsz) {
                const float* p = pb + k * 3;
                float dx = p[3] - p[0], dy = p[4] - p[1], dz = p[5] - p[2];
                s += sqrtf(fmaf(dx, dx, fmaf(dy, dy, dz * dz)));
            }
        }
        red[tid] = s; __syncthreads();
        for (int o = TPB / 2; o > 0; o >>= 1) {
            if (tid < o) red[tid] += red[tid + o];
            __syncthreads();
        }
        if (tid == 0) g_part[1 * SL_BLOCKS + blockIdx.x] = red[0];
        __syncthreads();

        // symmetry
        s = 0.f;
        const int mid = N_ / 2;
        for (int b = 0; b < B_; b++) {
            const float* pb = pred + b * N_ * 3;
            for (int k = gid; k < mid; k += gsz) {
                const float* l = pb + k * 3;
                const float* r = pb + (N_ - 1 - k) * 3;
                float d0 = l[0] + r[0];
                float d1 = l[1] - r[1];
                float d2 = l[2] - r[2];
                s += fmaf(d0, d0, fmaf(d1, d1, d2 * d2));
            }
        }
        red[tid] = s; __syncthreads();
        for (int o = TPB / 2; o > 0; o >>= 1) {
            if (tid < o) red[tid] += red[tid + o];
            __syncthreads();
        }
        if (tid == 0) g_part[2 * SL_BLOCKS + blockIdx.x] = red[0];
        return;
    }

    // ======== symmetric-fused chamfer ========
    const int cc = blockIdx.x - SL_BLOCKS;
    const int xt = cc & (XT - 1);
    const int ys = (cc >> 3) & (YS - 1);
    const int b  = cc >> 7;
    const int lane = tid & 31;
    const int wid  = tid >> 5;

    // load + fold targ segment (512 y)
    const float* Yb = targ + b * N_ * 3;
    const int m0 = ys * SEG;
    for (int j = tid; j < SEG; j += TPB) {
        const float* y = Yb + (m0 + j) * 3;
        float y0 = y[0], y1 = y[1], y2 = y[2];
        float yw = fmaf(y0, y0, fmaf(y1, y1, y2 * y2));
        sy[j][0] = dup2(-2.f * y0);
        sy[j][1] = dup2(-2.f * y1);
        sy[j][2] = dup2(-2.f * y2);
        sy[j][3] = dup2(yw);
    }
    __syncthreads();

    // load 4 pred points/thread as 2 packed pairs (q, q+2)
    const float* Xb = pred + b * N_ * 3;
    const int pbase = xt * XPB + tid;

    F2 xp0[2], xp1[2], xp2[2], xnp[2];
    float rmA[2], rmB[2];
#pragma unroll
    for (int q = 0; q < 2; q++) {
        const float* xa = Xb + (pbase + q * TPB) * 3;
        const float* xb = Xb + (pbase + (q + 2) * TPB) * 3;
        float a0 = xa[0], a1 = xa[1], a2 = xa[2];
        float b0 = xb[0], b1 = xb[1], b2 = xb[2];
        xp0[q].f = make_float2(a0, b0);
        xp1[q].f = make_float2(a1, b1);
        xp2[q].f = make_float2(a2, b2);
        xnp[q].f = make_float2(fmaf(a0, a0, fmaf(a1, a1, a2 * a2)),
                               fmaf(b0, b0, fmaf(b1, b1, b2 * b2)));
        rmA[q] = 3.0e38f; rmB[q] = 3.0e38f;
    }

    // mainloop: j warp-uniform (broadcast LDS.128 x2); each warp writes
    // scol[wid][j] exactly once (no RMW, no init, no races).
#pragma unroll 2
    for (int j = 0; j < SEG; j++) {
        const ulonglong2* row = (const ulonglong2*)sy[j];
        const ulonglong2 r0 = row[0];   // {-2y0 | -2y1}
        const ulonglong2 r1 = row[1];   // {-2y2 |  yw }
        F2 d0, d1;
        d0.u = fma2(xp0[0].u, r0.x,
               fma2(xp1[0].u, r0.y,
                fma2(xp2[0].u, r1.x, add2(xnp[0].u, r1.y))));
        d1.u = fma2(xp0[1].u, r0.x,
               fma2(xp1[1].u, r0.y,
                fma2(xp2[1].u, r1.x, add2(xnp[1].u, r1.y))));
        rmA[0] = fminf(rmA[0], d0.f.x);
        rmB[0] = fminf(rmB[0], d0.f.y);
        rmA[1] = fminf(rmA[1], d1.f.x);
        rmB[1] = fminf(rmB[1], d1.f.y);
        // col fold: clamp >= 0 FIRST (reference sqrt(max(d2,0)); also makes
        // the int-encoded REDUX ordering exact), then warp-min.
        float f = fminf(fminf(d0.f.x, d0.f.y), fminf(d1.f.x, d1.f.y));
        f = fmaxf(f, 0.f);
        int m = __reduce_min_sync(0xffffffffu, __float_as_int(f));
        if (lane == 0) scol[wid][j] = __int_as_float(m);
    }

    // pred-side partial mins (single writer, plain store)
#pragma unroll
    for (int q = 0; q < 2; q++) {
        g_rowpart[ys * (B_ * N_) + b * N_ + pbase + q * TPB]       = fmaxf(rmA[q], 0.f);
        g_rowpart[ys * (B_ * N_) + b * N_ + pbase + (q + 2) * TPB] = fmaxf(rmB[q], 0.f);
    }

    // targ-side: merge 8 warp-private arrays, plain store
    __syncthreads();
    for (int jj = tid; jj < SEG; jj += TPB) {
        float m = scol[0][jj];
#pragma unroll
        for (int w = 1; w < NWARP; w++) m = fminf(m, scol[w][jj]);
        g_colpart[xt * (B_ * N_) + b * N_ + m0 + jj] = m;  // already clamped
    }
}

// ---------------- reduce: fold partial mins, sqrt, block-sum ----------------
__global__ void reduce_kernel() {
    __shared__ float red[TPB];
    const int tid = threadIdx.x;
    const int gid = blockIdx.x * TPB + tid;
    const int gsz = RED_BLOCKS * TPB;   // 16384

    float s = 0.f;
    // pred side: 32768 points, fold 16 segments
    for (int i = gid; i < B_ * N_; i += gsz) {
        float m = g_rowpart[i];
#pragma unroll
        for (int t = 1; t < YS; t++) m = fminf(m, g_rowpart[t * (B_ * N_) + i]);
        s += sqrtf(m);
    }
    // targ side: 32768 points, fold 8 tiles
    for (int i = gid; i < B_ * N_; i += gsz) {
        float m = g_colpart[i];
#pragma unroll
        for (int t = 1; t < XT; t++) m = fminf(m, g_colpart[t * (B_ * N_) + i]);
        s += sqrtf(m);
    }
    red[tid] = s; __syncthreads();
    for (int o = TPB / 2; o > 0; o >>= 1) {
        if (tid < o) red[tid] += red[tid + o];
        __syncthreads();
    }
    if (tid == 0) g_part2[blockIdx.x] = red[0];
}

// ---------------- final scalar ----------------
__global__ void final_kernel(float* __restrict__ out) {
    __shared__ float red[TPB];
    __shared__ float sums[4];
    const int tid = threadIdx.x;

    float s = (tid < RED_BLOCKS) ? g_part2[tid] : 0.f;
    red[tid] = s; __syncthreads();
    for (int o = TPB / 2; o > 0; o >>= 1) {
        if (tid < o) red[tid] += red[tid + o];
        __syncthreads();
    }
    if (tid == 0) sums[3] = red[0];
    __syncthreads();

#pragma unroll
    for (int t = 0; t < 3; t++) {
        s = (tid < SL_BLOCKS) ? g_part[t * SL_BLOCKS + tid] : 0.f;
        red[tid] = s; __syncthreads();
        for (int o = TPB / 2; o > 0; o >>= 1) {
            if (tid < o) red[tid] += red[tid + o];
            __syncthreads();
        }
        if (tid == 0) sums[t] = red[0];
        __syncthreads();
    }

    if (tid == 0) {
        float vertex_loss  = sums[0] / (float)(B_ * N_ * 3);
        float smooth_loss  = sums[1] / (float)(B_ * (N_ - 1));
        float sym_loss     = sums[2] / (float)(B_ * (N_ / 2) * 3);
        float chamfer_loss = sums[3] / (float)(B_ * N_);
        out[0] = 1.0f * vertex_loss + 0.1f * smooth_loss
               + 0.05f * sym_loss + 0.1f * chamfer_loss;
    }
}

extern "C" void kernel_launch(void* const* d_in, const int* in_sizes, int n_in,
                              void* d_out, int out_size) {
    const float* pred = (const float*)d_in[0];
    const float* targ = (const float*)d_in[1];
    float* out = (float*)d_out;
    (void)in_sizes; (void)n_in; (void)out_size;

    mega_kernel<<<SL_BLOCKS + CHAM_BLOCKS, TPB>>>(pred, targ);
    reduce_kernel<<<RED_BLOCKS, TPB>>>();
    final_kernel<<<1, TPB>>>(out);
}

// round 6
// speedup vs baseline: 1.9875x; 1.2203x over previous
#include <cuda_runtime.h>
#include <math.h>

#define B_ 4
#define N_ 8192

constexpr int TPB   = 128;              // threads per block
constexpr int PPT   = 8;                // x per thread (4 packed pairs)
constexpr int XPB   = TPB * PPT;        // 1024 x per block
constexpr int XT    = N_ / XPB;         // 8 x tiles
constexpr int SEG   = 256;              // y per block
constexpr int YS    = N_ / SEG;         // 32 y segments
constexpr int NWARP = TPB / 32;         // 4
constexpr int CHAM_BLOCKS = XT * YS * B_;   // 1024
constexpr int SL_BLOCKS   = 160;            // 1024+160 = 1184 = 8*148
constexpr int RED_BLOCKS  = 64;
constexpr int FTPB  = 256;

// Partial-min scratch: every slot written exactly once per call (no init/atomics).
__device__ float g_rowpart[YS * B_ * N_];   // pred-side mins per y-segment (4MB)
__device__ float g_colpart[XT * B_ * N_];   // targ-side mins per x-tile   (1MB)
__device__ float g_part[3 * SL_BLOCKS];     // small-loss block partials
__device__ float g_part2[RED_BLOCKS];       // chamfer sqrt-sum partials

union F2 { unsigned long long u; float2 f; };

__device__ __forceinline__ unsigned long long fma2(unsigned long long a,
                                                   unsigned long long b,
                                                   unsigned long long c) {
    unsigned long long d;
    asm("fma.rn.f32x2 %0, %1, %2, %3;" : "=l"(d) : "l"(a), "l"(b), "l"(c));
    return d;
}
__device__ __forceinline__ unsigned long long add2(unsigned long long a,
                                                   unsigned long long b) {
    unsigned long long d;
    asm("add.rn.f32x2 %0, %1, %2;" : "=l"(d) : "l"(a), "l"(b));
    return d;
}
__device__ __forceinline__ unsigned long long dup2(float v) {
    F2 r; r.f = make_float2(v, v); return r.u;
}

// ------------- megakernel: 160 small-loss blocks + 1024 chamfer blocks -------------
__global__ void __launch_bounds__(TPB, 8)
mega_kernel(const float* __restrict__ pred, const float* __restrict__ targ) {
    // 32B per y row: [0]=-2y0 dup, [1]=-2y1 dup, [2]=-2y2 dup, [3]=yw dup
    __shared__ __align__(16) unsigned long long sy[SEG][4];   // 8KB
    __shared__ float scol[NWARP][SEG];                        // 4KB
    __shared__ float red[TPB];                                // .5KB

    const int tid = threadIdx.x;

    if (blockIdx.x < SL_BLOCKS) {
        // ======== small losses ========
        const int gid = blockIdx.x * TPB + tid;
        const int gsz = SL_BLOCKS * TPB;          // 20480

        const float4* p4 = (const float4*)pred;
        const float4* t4 = (const float4*)targ;
        float s = 0.f;
        for (int i = gid; i < B_ * N_ * 3 / 4; i += gsz) {
            float4 a = p4[i], b = t4[i];
            float d0 = a.x - b.x, d1 = a.y - b.y, d2 = a.z - b.z, d3 = a.w - b.w;
            s = fmaf(d0, d0, fmaf(d1, d1, fmaf(d2, d2, fmaf(d3, d3, s))));
        }
        red[tid] = s; __syncthreads();
        for (int o = TPB / 2; o > 0; o >>= 1) {
            if (tid < o) red[tid] += red[tid + o];
            __syncthreads();
        }
        if (tid == 0) g_part[0 * SL_BLOCKS + blockIdx.x] = red[0];
        __syncthreads();

        // smoothness
        s = 0.f;
        for (int b = 0; b < B_; b++) {
            const float* pb = pred + b * N_ * 3;
            for (int k = gid; k < N_ - 1; k += gsz) {
                const float* p = pb + k * 3;
                float dx = p[3] - p[0], dy = p[4] - p[1], dz = p[5] - p[2];
                s += sqrtf(fmaf(dx, dx, fmaf(dy, dy, dz * dz)));
            }
        }
        red[tid] = s; __syncthreads();
        for (int o = TPB / 2; o > 0; o >>= 1) {
            if (tid < o) red[tid] += red[tid + o];
            __syncthreads();
        }
        if (tid == 0) g_part[1 * SL_BLOCKS + blockIdx.x] = red[0];
        __syncthreads();

        // symmetry
        s = 0.f;
        const int mid = N_ / 2;
        for (int b = 0; b < B_; b++) {
            const float* pb = pred + b * N_ * 3;
            for (int k = gid; k < mid; k += gsz) {
                const float* l = pb + k * 3;
                const float* r = pb + (N_ - 1 - k) * 3;
                float d0 = l[0] + r[0];
                float d1 = l[1] - r[1];
                float d2 = l[2] - r[2];
                s += fmaf(d0, d0, fmaf(d1, d1, d2 * d2));
            }
        }
        red[tid] = s; __syncthreads();
        for (int o = TPB / 2; o > 0; o >>= 1) {
            if (tid < o) red[tid] += red[tid + o];
            __syncthreads();
        }
        if (tid == 0) g_part[2 * SL_BLOCKS + blockIdx.x] = red[0];
        return;
    }

    // ======== symmetric-fused chamfer ========
    const int cc = blockIdx.x - SL_BLOCKS;
    const int xt = cc & (XT - 1);            // 8
    const int ys = (cc >> 3) & (YS - 1);     // 32
    const int b  = cc >> 8;                  // 4
    const int lane = tid & 31;
    const int wid  = tid >> 5;

    // load + fold targ segment (256 y)
    const float* Yb = targ + b * N_ * 3;
    const int m0 = ys * SEG;
    for (int j = tid; j < SEG; j += TPB) {
        const float* y = Yb + (m0 + j) * 3;
        float y0 = y[0], y1 = y[1], y2 = y[2];
        float yw = fmaf(y0, y0, fmaf(y1, y1, y2 * y2));
        sy[j][0] = dup2(-2.f * y0);
        sy[j][1] = dup2(-2.f * y1);
        sy[j][2] = dup2(-2.f * y2);
        sy[j][3] = dup2(yw);
    }
    __syncthreads();

    // load 8 pred points/thread as 4 packed pairs (p, p+4)
    const float* Xb = pred + b * N_ * 3;
    const int pbase = xt * XPB + tid;

    F2 xp0[4], xp1[4], xp2[4], xnp[4];
    float rmA[4], rmB[4];
#pragma unroll
    for (int p = 0; p < 4; p++) {
        const float* xa = Xb + (pbase + p * TPB) * 3;
        const float* xb = Xb + (pbase + (p + 4) * TPB) * 3;
        float a0 = xa[0], a1 = xa[1], a2 = xa[2];
        float b0 = xb[0], b1 = xb[1], b2 = xb[2];
        xp0[p].f = make_float2(a0, b0);
        xp1[p].f = make_float2(a1, b1);
        xp2[p].f = make_float2(a2, b2);
        xnp[p].f = make_float2(fmaf(a0, a0, fmaf(a1, a1, a2 * a2)),
                               fmaf(b0, b0, fmaf(b1, b1, b2 * b2)));
        rmA[p] = 3.0e38f; rmB[p] = 3.0e38f;
    }

    // mainloop: j warp-uniform (broadcast LDS.128 x2); each warp writes
    // scol[wid][j] exactly once (no RMW, no init, no races).
#pragma unroll 2
    for (int j = 0; j < SEG; j++) {
        const ulonglong2* row = (const ulonglong2*)sy[j];
        const ulonglong2 r0 = row[0];   // {-2y0 | -2y1}
        const ulonglong2 r1 = row[1];   // {-2y2 |  yw }
        F2 d0, d1, d2, d3;
        d0.u = fma2(xp0[0].u, r0.x, fma2(xp1[0].u, r0.y,
                fma2(xp2[0].u, r1.x, add2(xnp[0].u, r1.y))));
        d1.u = fma2(xp0[1].u, r0.x, fma2(xp1[1].u, r0.y,
                fma2(xp2[1].u, r1.x, add2(xnp[1].u, r1.y))));
        d2.u = fma2(xp0[2].u, r0.x, fma2(xp1[2].u, r0.y,
                fma2(xp2[2].u, r1.x, add2(xnp[2].u, r1.y))));
        d3.u = fma2(xp0[3].u, r0.x, fma2(xp1[3].u, r0.y,
                fma2(xp2[3].u, r1.x, add2(xnp[3].u, r1.y))));
        rmA[0] = fminf(rmA[0], d0.f.x);  rmB[0] = fminf(rmB[0], d0.f.y);
        rmA[1] = fminf(rmA[1], d1.f.x);  rmB[1] = fminf(rmB[1], d1.f.y);
        rmA[2] = fminf(rmA[2], d2.f.x);  rmB[2] = fminf(rmB[2], d2.f.y);
        rmA[3] = fminf(rmA[3], d3.f.x);  rmB[3] = fminf(rmB[3], d3.f.y);
        // col fold (8 -> 1), clamp >= 0 (matches reference max(d2,0); also
        // makes int-encoded REDUX ordering exact), then warp-min.
        float f = fminf(fminf(fminf(d0.f.x, d0.f.y), fminf(d1.f.x, d1.f.y)),
                        fminf(fminf(d2.f.x, d2.f.y), fminf(d3.f.x, d3.f.y)));
        f = fmaxf(f, 0.f);
        int m = __reduce_min_sync(0xffffffffu, __float_as_int(f));
        if (lane == 0) scol[wid][j] = __int_as_float(m);
    }

    // pred-side partial mins (single writer, plain store)
#pragma unroll
    for (int p = 0; p < 4; p++) {
        g_rowpart[ys * (B_ * N_) + b * N_ + pbase + p * TPB]       = fmaxf(rmA[p], 0.f);
        g_rowpart[ys * (B_ * N_) + b * N_ + pbase + (p + 4) * TPB] = fmaxf(rmB[p], 0.f);
    }

    // targ-side: merge 4 warp-private arrays, plain store
    __syncthreads();
    for (int jj = tid; jj < SEG; jj += TPB) {
        float m = scol[0][jj];
#pragma unroll
        for (int w = 1; w < NWARP; w++) m = fminf(m, scol[w][jj]);
        g_colpart[xt * (B_ * N_) + b * N_ + m0 + jj] = m;  // already clamped
    }
}

// ---------------- reduce: fold partial mins, sqrt, block-sum ----------------
__global__ void reduce_kernel() {
    __shared__ float red[FTPB];
    const int tid = threadIdx.x;
    const int gid = blockIdx.x * FTPB + tid;
    const int gsz = RED_BLOCKS * FTPB;   // 16384

    float s = 0.f;
    for (int i = gid; i < B_ * N_; i += gsz) {
        float m = g_rowpart[i];
#pragma unroll
        for (int t = 1; t < YS; t++) m = fminf(m, g_rowpart[t * (B_ * N_) + i]);
        s += sqrtf(m);
    }
    for (int i = gid; i < B_ * N_; i += gsz) {
        float m = g_colpart[i];
#pragma unroll
        for (int t = 1; t < XT; t++) m = fminf(m, g_colpart[t * (B_ * N_) + i]);
        s += sqrtf(m);
    }
    red[tid] = s; __syncthreads();
    for (int o = FTPB / 2; o > 0; o >>= 1) {
        if (tid < o) red[tid] += red[tid + o];
        __syncthreads();
    }
    if (tid == 0) g_part2[blockIdx.x] = red[0];
}

// ---------------- final scalar ----------------
__global__ void final_kernel(float* __restrict__ out) {
    __shared__ float red[FTPB];
    __shared__ float sums[4];
    const int tid = threadIdx.x;

    float s = (tid < RED_BLOCKS) ? g_part2[tid] : 0.f;
    red[tid] = s; __syncthreads();
    for (int o = FTPB / 2; o > 0; o >>= 1) {
        if (tid < o) red[tid] += red[tid + o];
        __syncthreads();
    }
    if (tid == 0) sums[3] = red[0];
    __syncthreads();

#pragma unroll
    for (int t = 0; t < 3; t++) {
        s = (tid < SL_BLOCKS) ? g_part[t * SL_BLOCKS + tid] : 0.f;
        red[tid] = s; __syncthreads();
        for (int o = FTPB / 2; o > 0; o >>= 1) {
            if (tid < o) red[tid] += red[tid + o];
            __syncthreads();
        }
        if (tid == 0) sums[t] = red[0];
        __syncthreads();
    }

    if (tid == 0) {
        float vertex_loss  = sums[0] / (float)(B_ * N_ * 3);
        float smooth_loss  = sums[1] / (float)(B_ * (N_ - 1));
        float sym_loss     = sums[2] / (float)(B_ * (N_ / 2) * 3);
        float chamfer_loss = sums[3] / (float)(B_ * N_);
        out[0] = 1.0f * vertex_loss + 0.1f * smooth_loss
               + 0.05f * sym_loss + 0.1f * chamfer_loss;
    }
}

extern "C" void kernel_launch(void* const* d_in, const int* in_sizes, int n_in,
                              void* d_out, int out_size) {
    const float* pred = (const float*)d_in[0];
    const float* targ = (const float*)d_in[1];
    float* out = (float*)d_out;
    (void)in_sizes; (void)n_in; (void)out_size;

    mega_kernel<<<SL_BLOCKS + CHAM_BLOCKS, TPB>>>(pred, targ);  // 1184 = 8*148
    reduce_kernel<<<RED_BLOCKS, FTPB>>>();
    final_kernel<<<1, FTPB>>>(out);
}